// round 10
// baseline (speedup 1.0000x reference)
#include <cuda_runtime.h>

#define BATCH 16
#define NANCH 25200
#define NCLS  80
#define TOPK  2048
#define KW    32     // TOPK/64 words of keep/removed bits

typedef unsigned long long u64;
typedef unsigned int u32;

// ---------------- scratch (static device globals; no allocation) -------------
__device__ float  g_score[BATCH * NANCH];
__device__ int    g_label[BATCH * NANCH];
__device__ float4 g_top_boxes[BATCH * TOPK];
__device__ float  g_top_scores[BATCH * TOPK];
__device__ int    g_top_labels[BATCH * TOPK];
__device__ u64    g_keep[BATCH * KW];

// ---------------- IoU suppression predicate ----------------------------------
// Fast path: sign of inter - 0.45*union (FMA). Borderline (|d| <= 1e-5*union)
// falls back to IEEE division so the predicate is bit-identical to the
// reference's (inter/union > 0.45). IoU is symmetric in the two boxes.
__device__ __forceinline__ bool sup_pred(float4 rb, float ra, float4 c, float ca) {
    float ax = fmaxf(rb.x, c.x);
    float ay = fmaxf(rb.y, c.y);
    float bx = fminf(rb.z, c.z);
    float by = fminf(rb.w, c.w);
    float ww = fmaxf(__fadd_rn(bx, -ax), 0.0f);
    float hh = fmaxf(__fadd_rn(by, -ay), 0.0f);
    float inter = __fmul_rn(ww, hh);
    float uni = __fadd_rn(__fadd_rn(ra, ca), -inter);
    float d = __fmaf_rn(uni, -0.45f, inter);
    if (fabsf(d) > 1e-5f * uni) return d > 0.0f;
    return __fdiv_rn(inter, uni) > 0.45f;
}

// ---------------- stage 1: obj*cls max + argmax + conf filter ----------------
// Replicates: scores_all = obj[...,None]*probs; max/argmax over classes;
// conf filter (>0.25 else 0). Strict '>' ascending scan == first-occurrence
// argmax of the *rounded products* (matches jnp exactly).
__global__ void __launch_bounds__(256) k_score(const float* __restrict__ obj,
                                               const float* __restrict__ probs) {
    int t = blockIdx.x * 256 + threadIdx.x;
    if (t >= BATCH * NANCH) return;
    float o = obj[t];
    const float4* p = reinterpret_cast<const float4*>(probs) + (size_t)t * (NCLS / 4);
    float best = -1.0f;
    int bl = 0;
#pragma unroll
    for (int i = 0; i < NCLS / 4; i++) {
        float4 v = p[i];
        float s;
        s = __fmul_rn(o, v.x); if (s > best) { best = s; bl = 4 * i + 0; }
        s = __fmul_rn(o, v.y); if (s > best) { best = s; bl = 4 * i + 1; }
        s = __fmul_rn(o, v.z); if (s > best) { best = s; bl = 4 * i + 2; }
        s = __fmul_rn(o, v.w); if (s > best) { best = s; bl = 4 * i + 3; }
    }
    g_score[t] = (best > 0.25f) ? best : 0.0f;
    g_label[t] = bl;
}

// ---------------- stage 2: stable top-2048 per image -------------------------
// Histogram on score bits -> threshold bin -> compact -> 4096-wide bitonic
// sort on key=(bits<<16)|(65535-idx): stable top-K identical to jax.lax.top_k.
__global__ void __launch_bounds__(1024) k_topk(const float* __restrict__ boxes) {
    __shared__ u32 hist[2048];
    __shared__ u64 buf[4096];
    __shared__ int shT;
    __shared__ u32 shCnt;
    int b = blockIdx.x;
    int tid = threadIdx.x;
    const float* sc = g_score + (size_t)b * NANCH;

    hist[tid] = 0u; hist[tid + 1024] = 0u;
    if (tid == 0) { shT = 0; shCnt = 0u; }
    __syncthreads();

    for (int n = tid; n < NANCH; n += 1024) {
        float s = sc[n];
        if (s > 0.0f) {
            u32 bits = __float_as_uint(s);
            u32 bin = (bits - 0x3E800000u) >> 13;
            if (bin > 2047u) bin = 2047u;
            atomicAdd(&hist[bin], 1u);
        }
    }
    __syncthreads();

    for (int off = 1; off < 2048; off <<= 1) {
        u32 v0 = (tid + off < 2048) ? hist[tid + off] : 0u;
        u32 v1 = (tid + 1024 + off < 2048) ? hist[tid + 1024 + off] : 0u;
        __syncthreads();
        hist[tid] += v0;
        hist[tid + 1024] += v1;
        __syncthreads();
    }

    for (int bb = tid; bb < 2048; bb += 1024) {
        u32 sb = hist[bb];
        u32 sb1 = (bb == 2047) ? 0u : hist[bb + 1];
        if (sb >= (u32)TOPK && sb1 < (u32)TOPK) shT = bb;
    }
    __syncthreads();
    u32 T = (u32)shT;

    for (int n = tid; n < NANCH; n += 1024) {
        float s = sc[n];
        if (s > 0.0f) {
            u32 bits = __float_as_uint(s);
            u32 bin = (bits - 0x3E800000u) >> 13;
            if (bin > 2047u) bin = 2047u;
            if (bin >= T) {
                u32 pos = atomicAdd(&shCnt, 1u);
                if (pos < 4096u) buf[pos] = ((u64)bits << 16) | (u64)(u32)(65535 - n);
            }
        }
    }
    __syncthreads();
    u32 M = shCnt; if (M > 4096u) M = 4096u;
    for (u32 i = M + tid; i < 4096u; i += 1024u) buf[i] = 0ull;

    for (u32 kk = 2; kk <= 4096; kk <<= 1) {
        for (u32 j = kk >> 1; j > 0; j >>= 1) {
            __syncthreads();
            for (u32 i = tid; i < 4096; i += 1024) {
                u32 l = i ^ j;
                if (l > i) {
                    u64 a = buf[i], c = buf[l];
                    bool dir = ((i & kk) == 0);
                    if ((a < c) == dir) { buf[i] = c; buf[l] = a; }
                }
            }
        }
    }
    __syncthreads();

    for (int k = tid; k < TOPK; k += 1024) {
        u64 key = buf[k];
        u32 bits = (u32)(key >> 16);
        float4 bx = make_float4(0.f, 0.f, 0.f, 0.f);
        float s = 0.0f;
        int lab = 0;
        if (bits != 0u) {
            int idx = 65535 - (int)(key & 0xFFFFull);
            s = __uint_as_float(bits);
            bx = reinterpret_cast<const float4*>(boxes)[(size_t)b * NANCH + idx];
            lab = g_label[(size_t)b * NANCH + idx];
        }
        g_top_boxes[b * TOPK + k] = bx;
        g_top_scores[b * TOPK + k] = s;
        g_top_labels[b * TOPK + k] = lab;
    }
}

// ---------------- stage 3: fused IoU + greedy NMS ----------------------------
// 1 CTA (1024 thr) per image; all 2048 boxes+areas smem-resident (40 KB).
// 32 blocks of 64 rows, ascending. Per block:
//   parallel phase: (a) 32 warps compute the 64x64 diagonal suppression words
//                       via 4 IoU evals/lane + 2 ballots (j>i masked);
//                   (b) previous block's ACCEPTED rows are applied to all later
//                       columns: per-column early-break scan over the accepted
//                       bitmask, atomicOr into rem[]. Work ~ #accepted, not N^2.
//   serial phase (thread 0): 64-step greedy resolve (reference accept order).
__global__ void __launch_bounds__(1024) k_nms() {
    __shared__ float4 sb[TOPK];   // 32 KB boxes
    __shared__ float  sa[TOPK];   //  8 KB areas
    __shared__ u64 diag[64];
    __shared__ u64 rem[KW];
    __shared__ u64 accsh;

    int b = blockIdx.x;
    int tid = threadIdx.x;
    int w = tid >> 5;
    int lane = tid & 31;
    const float* ts = g_top_scores + b * TOPK;

    // stage boxes + areas (area exactly as reference: (x2-x1)*(y2-y1))
    for (int i = tid; i < TOPK; i += 1024) {
        float4 v = g_top_boxes[b * TOPK + i];
        sb[i] = v;
        sa[i] = __fmul_rn(__fadd_rn(v.z, -v.x), __fadd_rn(v.w, -v.y));
    }
    // seed rem with conf-dead bits (warp w -> word w)
    {
        bool a0 = ts[w * 64 + lane] > 0.0f;
        bool a1 = ts[w * 64 + 32 + lane] > 0.0f;
        u32 lo = __ballot_sync(0xffffffffu, a0);
        u32 hi = __ballot_sync(0xffffffffu, a1);
        if (lane == 0) rem[w] = ~(((u64)hi << 32) | (u64)lo);
    }
    __syncthreads();

    u64 acc_prev = 0ull;
    int base_prev = 0;

    for (int blk = 0; blk < KW; blk++) {
        int base = blk * 64;

        // ---- parallel phase (a): diagonal words for this block ----
        // warp w owns local rows w and w+32
#pragma unroll
        for (int rr = 0; rr < 2; rr++) {
            int rl = w + rr * 32;
            float4 rb = sb[base + rl];
            float ra = sa[base + rl];
            bool s0 = sup_pred(rb, ra, sb[base + lane],      sa[base + lane]);
            bool s1 = sup_pred(rb, ra, sb[base + 32 + lane], sa[base + 32 + lane]);
            u64 wbits = ((u64)__ballot_sync(0xffffffffu, s1) << 32)
                      |  (u64)__ballot_sync(0xffffffffu, s0);
            wbits &= (rl == 63) ? 0ull : (~0ull << (rl + 1));   // j > i only
            if (lane == 0) diag[rl] = wbits;
        }

        // ---- parallel phase (b): previous block's accepted rows -> later cols
        if (acc_prev) {
            for (int j = base + tid; j < TOPK; j += 1024) {
                float4 cb = sb[j];
                float ca = sa[j];
                u64 a = acc_prev;
                bool s = false;
                while (a) {
                    int k = __ffsll((long long)a) - 1;
                    a &= a - 1ull;
                    int i = base_prev + k;
                    if (sup_pred(sb[i], sa[i], cb, ca)) { s = true; break; }
                }
                if (s) atomicOr(&rem[j >> 6], 1ull << (j & 63));
            }
        }
        __syncthreads();   // diag + rem updates visible

        // ---- serial phase: greedy resolve of this block ----
        if (tid == 0) {
            u64 removed = rem[blk];
#pragma unroll 16
            for (int k = 0; k < 64; k++) {
                if (!((removed >> k) & 1ull)) removed |= diag[k];
            }
            rem[blk] = removed;
            accsh = ~removed;
        }
        __syncthreads();   // accsh visible

        acc_prev = accsh;
        base_prev = base;
    }

    if (tid < KW) g_keep[b * KW + tid] = ~rem[tid];
}

// ---------------- stage 4: finalize outputs ----------------------------------
// d_out layout (flattened tuple, float32): boxes[16,2048,4] | scores[16,2048]
// | labels[16,2048] (labels value-cast to float).
__global__ void __launch_bounds__(256) k_final(float* __restrict__ out) {
    int t = blockIdx.x * 256 + threadIdx.x;
    if (t >= BATCH * TOPK) return;
    int b = t / TOPK, k = t % TOPK;
    u64 kw = g_keep[b * KW + (k >> 6)];
    bool keep = ((kw >> (k & 63)) & 1ull) != 0ull;
    float4 bx = g_top_boxes[t];
    float s = g_top_scores[t];
    int lab = g_top_labels[t];
    reinterpret_cast<float4*>(out)[t] = keep ? bx : make_float4(0.f, 0.f, 0.f, 0.f);
    out[BATCH * TOPK * 4 + t] = keep ? s : 0.0f;
    out[BATCH * TOPK * 5 + t] = keep ? (float)lab : 0.0f;
}

// ---------------- launch ------------------------------------------------------
extern "C" void kernel_launch(void* const* d_in, const int* in_sizes, int n_in,
                              void* d_out, int out_size) {
    const float* boxes = (const float*)d_in[0];
    const float* obj   = (const float*)d_in[1];
    const float* probs = (const float*)d_in[2];

    k_score<<<(BATCH * NANCH + 255) / 256, 256>>>(obj, probs);
    k_topk<<<BATCH, 1024>>>(boxes);
    k_nms<<<BATCH, 1024>>>();
    k_final<<<(BATCH * TOPK + 255) / 256, 256>>>((float*)d_out);
}